// round 16
// baseline (speedup 1.0000x reference)
#include <cuda_runtime.h>
#include <cuda_fp16.h>
#include <math.h>
#include <cstdint>

#define BATCH  4
#define NQ     1024
#define NKV    2048
#define DMODEL 1024
#define HEADS  16
#define DH     64
#define INNER  1024
#define KDIM   1024

// ---------------- scratch (no allocation allowed) ----------------
__device__ __half g_xn [BATCH * NQ  * DMODEL];
__device__ __half g_q  [BATCH * NQ  * INNER];
__device__ __half g_k  [BATCH * NKV * INNER];
__device__ __half g_v  [BATCH * NKV * INNER];
__device__ __half g_ctx[BATCH * NQ  * INNER];
__device__ __half g_wqt[KDIM * INNER];
__device__ __half g_wkt[KDIM * INNER];
__device__ __half g_wvt[KDIM * INNER];
__device__ __half g_wot[KDIM * INNER];
__device__ __half g_kin[BATCH * NKV * KDIM];
__device__ __half g_vin[BATCH * NKV * KDIM];
__device__ unsigned long long g_mb[BATCH * 32 * NQ];   // [b][kvblock][q] bitmask

__device__ __forceinline__ uint32_t smem_to_u32(const void* p) {
    uint32_t a;
    asm("{ .reg .u64 t; cvta.to.shared.u64 t, %1; cvt.u32.u64 %0, t; }" : "=r"(a) : "l"(p));
    return a;
}
__device__ __forceinline__ void cp_async16(uint32_t saddr, const void* g) {
    asm volatile("cp.async.cg.shared.global [%0], [%1], 16;" :: "r"(saddr), "l"(g));
}
#define CP_COMMIT() asm volatile("cp.async.commit_group;")
#define CP_WAIT(n)  asm volatile("cp.async.wait_group %0;" :: "n"(n) : "memory")

#define MMA_F16(acc, a0, a1, a2, a3, b0, b1) \
    asm volatile( \
        "mma.sync.aligned.m16n8k16.row.col.f32.f16.f16.f32 " \
        "{%0,%1,%2,%3}, {%4,%5,%6,%7}, {%8,%9}, {%0,%1,%2,%3};" \
        : "+f"((acc)[0]), "+f"((acc)[1]), "+f"((acc)[2]), "+f"((acc)[3]) \
        : "r"(a0), "r"(a1), "r"(a2), "r"(a3), "r"(b0), "r"(b1))

#define LDSM_X4(r, addr) \
    asm volatile("ldmatrix.sync.aligned.m8n8.x4.shared.b16 {%0,%1,%2,%3}, [%4];" \
        : "=r"((r)[0]), "=r"((r)[1]), "=r"((r)[2]), "=r"((r)[3]) : "r"(addr))

#define LDSM_X4_T(r, addr) \
    asm volatile("ldmatrix.sync.aligned.m8n8.x4.trans.shared.b16 {%0,%1,%2,%3}, [%4];" \
        : "=r"((r)[0]), "=r"((r)[1]), "=r"((r)[2]), "=r"((r)[3]) : "r"(addr))

__device__ __forceinline__ uint32_t packh2(float a, float b) {
    __half2 h = __floats2half2_rn(a, b);
    return *(uint32_t*)&h;
}

// ---------------- fused prep: transposes + rounds + maskbits + LN -------------
__global__ void prep_fused(const float* __restrict__ x,
                           const float* __restrict__ key_t, const float* __restrict__ value,
                           const int* __restrict__ mask,
                           const float* __restrict__ Wq, const float* __restrict__ Wk,
                           const float* __restrict__ Wv, const float* __restrict__ Wo,
                           const float* __restrict__ gamma, const float* __restrict__ beta,
                           __half* __restrict__ xn,
                           __half* __restrict__ kin, __half* __restrict__ vin,
                           unsigned long long* __restrict__ mb,
                           __half* __restrict__ wqt, __half* __restrict__ wkt,
                           __half* __restrict__ wvt, __half* __restrict__ wot) {
    __shared__ float smbuf[32][33];
    int bid = blockIdx.x, tid = threadIdx.x;

    if (bid < 4096) {                          // ---- weight transpose (to fp16)
        int w = bid >> 10, t = bid & 1023;
        const float* src = (w == 0) ? Wq : (w == 1) ? Wk : (w == 2) ? Wv : Wo;
        __half* dst      = (w == 0) ? wqt : (w == 1) ? wkt : (w == 2) ? wvt : wot;
        int bx = (t & 31) * 32, by = (t >> 5) * 32;
        int xI = tid & 31, yI = tid >> 5;      // 32 x 8
#pragma unroll
        for (int i = 0; i < 32; i += 8)
            smbuf[yI + i][xI] = src[(size_t)(by + yI + i) * KDIM + bx + xI];
        __syncthreads();
#pragma unroll
        for (int i = 0; i < 32; i += 8)
            dst[(size_t)(bx + yI + i) * KDIM + by + xI] = __float2half_rn(smbuf[xI][yI + i]);
    } else if (bid < 20480) {                  // ---- fp32 -> fp16 round
        int i0 = bid - 4096;
        const float* src = (i0 < 8192) ? key_t : value;
        __half* dst      = (i0 < 8192) ? kin : vin;
        int i = (i0 & 8191) * 256 + tid;
        float4 v = ((const float4*)src)[i];
        ((__half2*)dst)[2 * i]     = __floats2half2_rn(v.x, v.y);
        ((__half2*)dst)[2 * i + 1] = __floats2half2_rn(v.z, v.w);
    } else if (bid < 20992) {                  // ---- mask -> bitmask
        int idx = (bid - 20480) * 256 + tid;
        int b = idx >> 15, t = (idx >> 10) & 31, q = idx & 1023;
        const int4* p = (const int4*)(mask + (((size_t)b * NQ + q) * NKV + t * 64));
        unsigned long long bits = 0ull;
#pragma unroll
        for (int j = 0; j < 16; j++) {
            int4 v = p[j];
            bits |= (unsigned long long)(v.x != 0) << (4 * j);
            bits |= (unsigned long long)(v.y != 0) << (4 * j + 1);
            bits |= (unsigned long long)(v.z != 0) << (4 * j + 2);
            bits |= (unsigned long long)(v.w != 0) << (4 * j + 3);
        }
        mb[idx] = bits;
    } else {                                   // ---- LayerNorm (fp16 out)
        float* red = &smbuf[0][0];
        int row = bid - 20992;
        const float4* xr = (const float4*)(x + (size_t)row * DMODEL);
        float4 a = xr[tid];
        float s = a.x + a.y + a.z + a.w;
        float q = a.x * a.x + a.y * a.y + a.z * a.z + a.w * a.w;
#pragma unroll
        for (int off = 16; off; off >>= 1) {
            s += __shfl_xor_sync(0xffffffffu, s, off);
            q += __shfl_xor_sync(0xffffffffu, q, off);
        }
        if ((tid & 31) == 0) { red[tid >> 5] = s; red[8 + (tid >> 5)] = q; }
        __syncthreads();
        if (tid < 32) {
            float ss = (tid < 8) ? red[tid] : 0.f;
            float qq = (tid < 8) ? red[8 + tid] : 0.f;
#pragma unroll
            for (int off = 4; off; off >>= 1) {
                ss += __shfl_xor_sync(0xffffffffu, ss, off);
                qq += __shfl_xor_sync(0xffffffffu, qq, off);
            }
            if (tid == 0) { red[0] = ss; red[1] = qq; }
        }
        __syncthreads();
        float mu  = red[0] * (1.f / DMODEL);
        float var = red[1] * (1.f / DMODEL) - mu * mu;
        float inv = rsqrtf(var + 1e-5f);
        float4 g = ((const float4*)gamma)[tid];
        float4 b = ((const float4*)beta)[tid];
        __half2* yr = (__half2*)(xn + (size_t)row * DMODEL);
        yr[2 * tid]     = __floats2half2_rn((a.x - mu) * inv * g.x + b.x, (a.y - mu) * inv * g.y + b.y);
        yr[2 * tid + 1] = __floats2half2_rn((a.z - mu) * inv * g.z + b.z, (a.w - mu) * inv * g.w + b.w);
    }
}

// ---------------- fp16 mma GEMM core (cp.async, 3-stage pipeline) -------------
#define GROW 144
#define GBUF_B (128 * GROW)
#define GT_SMEM (6 * GBUF_B)     // 3 stages x (A+B) = 110592 B

__device__ __forceinline__ void gemm_core(const __half* __restrict__ Ab,
                                          const __half* __restrict__ Bb,
                                          void* __restrict__ Cout, size_t crowbase,
                                          int half_out, uint32_t sb, uint32_t* smw) {
    int tid = threadIdx.x, lane = tid & 31, wid = tid >> 5;
    int wm = (wid & 3) * 32, wn = (wid >> 2) * 64;
    int mrow = lane & 7, msel = lane >> 3;

    uint32_t aoffB = (uint32_t)((wm + (msel & 1) * 8 + mrow) * GROW + (msel >> 1) * 16);
    uint32_t boffB = (uint32_t)((wn + (msel >> 1) * 8 + mrow) * GROW + (msel & 1) * 16);

    float acc[2][8][4] = {};

#define G_ISSUE(it, bf) do { \
    uint32_t abase = sb + (bf) * GBUF_B; \
    uint32_t bbase = sb + (3 + (bf)) * GBUF_B; \
    _Pragma("unroll") \
    for (int i = 0; i < 4; i++) { \
        int idx = tid + i * 256; int rr = idx >> 3, qq = idx & 7; \
        cp_async16(abase + rr * GROW + qq * 16, Ab + (size_t)rr * KDIM + (it) * 64 + qq * 8); \
        cp_async16(bbase + rr * GROW + qq * 16, Bb + (size_t)rr * KDIM + (it) * 64 + qq * 8); \
    } \
    CP_COMMIT(); \
} while (0)

    G_ISSUE(0, 0);
    G_ISSUE(1, 1);

    for (int it = 0; it < 16; it++) {
        int buf = it % 3;
        if (it < 15) CP_WAIT(1);
        else         CP_WAIT(0);
        __syncthreads();
        if (it < 14) G_ISSUE(it + 2, (it + 2) % 3);

        uint32_t aaddr = sb + buf * GBUF_B + aoffB;
        uint32_t baddr = sb + (3 + buf) * GBUF_B + boffB;
#pragma unroll
        for (int ks = 0; ks < 4; ks++) {
            uint32_t afr[2][4];
            LDSM_X4(afr[0], aaddr + ks * 32);
            LDSM_X4(afr[1], aaddr + 16 * GROW + ks * 32);
#pragma unroll
            for (int p = 0; p < 4; p++) {
                uint32_t bfr[4];
                LDSM_X4(bfr, baddr + p * (16 * GROW) + ks * 32);
#pragma unroll
                for (int sub = 0; sub < 2; sub++) {
                    int nf = 2 * p + sub;
                    uint32_t b0 = bfr[sub * 2], b1 = bfr[sub * 2 + 1];
#pragma unroll
                    for (int mf = 0; mf < 2; mf++)
                        MMA_F16(acc[mf][nf], afr[mf][0], afr[mf][1], afr[mf][2], afr[mf][3], b0, b1);
                }
            }
        }
    }
#undef G_ISSUE

    if (half_out) {
        __half* Cb = (__half*)Cout + crowbase;
#pragma unroll
        for (int mf = 0; mf < 2; mf++) {
            int row = wm + mf * 16 + (lane >> 2);
#pragma unroll
            for (int nf = 0; nf < 8; nf++) {
                int col = wn + nf * 8 + (lane & 3) * 2;
                *(__half2*)(Cb + (size_t)row * 1024 + col) =
                    __floats2half2_rn(acc[mf][nf][0], acc[mf][nf][1]);
                *(__half2*)(Cb + (size_t)(row + 8) * 1024 + col) =
                    __floats2half2_rn(acc[mf][nf][2], acc[mf][nf][3]);
            }
        }
    } else {
        float* Cb = (float*)Cout + crowbase;
#pragma unroll
        for (int mf = 0; mf < 2; mf++) {
            int row = wm + mf * 16 + (lane >> 2);
#pragma unroll
            for (int nf = 0; nf < 8; nf++) {
                int col = wn + nf * 8 + (lane & 3) * 2;
                *(float2*)(Cb + (size_t)row * 1024 + col) = make_float2(acc[mf][nf][0], acc[mf][nf][1]);
                *(float2*)(Cb + (size_t)(row + 8) * 1024 + col) = make_float2(acc[mf][nf][2], acc[mf][nf][3]);
            }
        }
    }
}

// merged QKV GEMM: grid y 0..159
__global__ void __launch_bounds__(256, 2)
gemm_qkv(const __half* __restrict__ xn, const __half* __restrict__ kin, const __half* __restrict__ vin,
         const __half* __restrict__ wqt, const __half* __restrict__ wkt, const __half* __restrict__ wvt,
         __half* __restrict__ q, __half* __restrict__ k, __half* __restrict__ v) {
    extern __shared__ uint32_t smw[];
    uint32_t sb = smem_to_u32(smw);
    int y = blockIdx.y;
    const __half *A, *B;
    __half* C;
    int ytile;
    if (y < 32)      { A = xn;  B = wqt; C = q; ytile = y; }
    else if (y < 96) { A = kin; B = wkt; C = k; ytile = y - 32; }
    else             { A = vin; B = wvt; C = v; ytile = y - 96; }
    gemm_core(A + (size_t)(ytile * 128) * KDIM,
              B + (size_t)(blockIdx.x * 128) * KDIM,
              C, (size_t)(ytile * 128) * 1024 + blockIdx.x * 128, 1, sb, smw);
}

__global__ void __launch_bounds__(256, 2)
gemm_out(const __half* __restrict__ ctx, const __half* __restrict__ wot, float* __restrict__ out) {
    extern __shared__ uint32_t smw[];
    uint32_t sb = smem_to_u32(smw);
    gemm_core(ctx + (size_t)(blockIdx.y * 128) * KDIM,
              wot + (size_t)(blockIdx.x * 128) * KDIM,
              out, (size_t)(blockIdx.y * 128) * 1024 + blockIdx.x * 128, 0, sb, smw);
}

// ---------------- fp16 mma flash attention: 128 q x 64 kv, 4 warps, 3 CTAs/SM -
#define QTILE 128
#define AROW 144
#define OFF_Q 0
#define SZ_Q  (QTILE * AROW)                 // 18432
#define OFF_K (SZ_Q)
#define SZ_KV (64 * AROW)                    // 9216
#define OFF_V (SZ_Q + 2 * SZ_KV)
#define OFF_M (SZ_Q + 4 * SZ_KV)             // 55296
#define ATTN_SMEM (OFF_M + 2 * 1024)         // 57344; x3 CTAs = 172032

__global__ void __launch_bounds__(128, 3)
attn_mma(const __half* __restrict__ Q,
         const __half* __restrict__ K,
         const __half* __restrict__ V,
         const unsigned long long* __restrict__ mbits,
         __half* __restrict__ ctx) {
    extern __shared__ uint32_t sw[];
    uint32_t sb = smem_to_u32(sw);

    int tid = threadIdx.x, lane = tid & 31, wid = tid >> 5;   // 4 warps
    int b = blockIdx.z, h = blockIdx.y, qt = blockIdx.x;
    const int g = lane >> 2, t4 = lane & 3;
    const int wm = wid * 32;
    const int mrow = lane & 7, msel = lane >> 3;

    const uint32_t qa0 = sb + OFF_Q + (uint32_t)((wm + (msel & 1) * 8 + mrow) * AROW + (msel >> 1) * 16);
    const uint32_t qa1 = qa0 + 16 * AROW;
    const uint32_t kfragoff = (uint32_t)(((msel >> 1) * 8 + mrow) * AROW + (msel & 1) * 16);
    const uint32_t vfragoff = (uint32_t)(((msel & 1) * 8 + mrow) * AROW + (msel >> 1) * 16);

    const __half* Qb = Q + ((size_t)b * NQ + qt * QTILE) * INNER + h * DH;
    const __half* Kb = K + (size_t)b * NKV * INNER + h * DH;
    const __half* Vb = V + (size_t)b * NKV * INNER + h * DH;
    const char* Mb8 = (const char*)(mbits + (size_t)b * 32 * NQ) + (size_t)qt * QTILE * 8;

    // issue Q tile: 128 rows x 8 segs = 1024 cp over 128 threads
#pragma unroll
    for (int i = 0; i < 8; i++) {
        int idx = tid + i * 128;
        int r = idx >> 3, qq = idx & 7;
        cp_async16(sb + OFF_Q + r * AROW + qq * 16, Qb + (size_t)r * INNER + qq * 8);
    }
    CP_COMMIT();

#define A_ISSUE(t, bf) do { \
    uint32_t kb_ = sb + OFF_K + (bf) * SZ_KV; \
    uint32_t vb_ = sb + OFF_V + (bf) * SZ_KV; \
    uint32_t mb_ = sb + OFF_M + (bf) * 1024; \
    _Pragma("unroll") \
    for (int i = 0; i < 4; i++) { \
        int idx = tid + i * 128; int r = idx >> 3, qq = idx & 7; \
        cp_async16(kb_ + r * AROW + qq * 16, Kb + (size_t)((t) * 64 + r) * INNER + qq * 8); \
        cp_async16(vb_ + r * AROW + qq * 16, Vb + (size_t)((t) * 64 + r) * INNER + qq * 8); \
    } \
    if (tid < 64) cp_async16(mb_ + tid * 16, Mb8 + (size_t)(t) * NQ * 8 + tid * 16); \
    CP_COMMIT(); \
} while (0)

    A_ISSUE(0, 0);

    float oacc[2][8][4] = {};
    float mrun[4], lrun[4];
#pragma unroll
    for (int i = 0; i < 4; i++) { mrun[i] = -3.402823466e38f; lrun[i] = 0.f; }
    const float scl = 0.125f;

    for (int t = 0; t < NKV / 64; t++) {
        int buf = t & 1;
        CP_WAIT(0);
        __syncthreads();
        if (t < 31) A_ISSUE(t + 1, buf ^ 1);

        const uint32_t kbase = sb + OFF_K + buf * SZ_KV + kfragoff;
        const uint32_t vbase = sb + OFF_V + buf * SZ_KV + vfragoff;
        const unsigned long long* Msk =
            (const unsigned long long*)((const char*)sw + OFF_M + buf * 1024);

        // ---- S = Q K^T (warp: 32 x 64, 4 x k16) ----
        float sacc[2][8][4] = {};
#pragma unroll
        for (int ks = 0; ks < 4; ks++) {
            uint32_t afr[2][4];
            LDSM_X4(afr[0], qa0 + ks * 32);
            LDSM_X4(afr[1], qa1 + ks * 32);
#pragma unroll
            for (int p = 0; p < 4; p++) {
                uint32_t bfr[4];
                LDSM_X4(bfr, kbase + p * (16 * AROW) + ks * 32);
#pragma unroll
                for (int sub = 0; sub < 2; sub++) {
                    int nf = 2 * p + sub;
                    uint32_t b0 = bfr[sub * 2], b1 = bfr[sub * 2 + 1];
#pragma unroll
                    for (int mf = 0; mf < 2; mf++)
                        MMA_F16(sacc[mf][nf], afr[mf][0], afr[mf][1], afr[mf][2], afr[mf][3], b0, b1);
                }
            }
        }

        // ---- mask + scale + online softmax; P packed into registers ----
        unsigned long long mbm[4];
        mbm[0] = Msk[wm + g];
        mbm[1] = Msk[wm + g + 8];
        mbm[2] = Msk[wm + g + 16];
        mbm[3] = Msk[wm + g + 24];
        int sh0 = t4 * 2;

        float tm[4];
#pragma unroll
        for (int i = 0; i < 4; i++) tm[i] = -3.402823466e38f;
#pragma unroll
        for (int mf = 0; mf < 2; mf++) {
            unsigned long long mlo = mbm[2 * mf], mhi = mbm[2 * mf + 1];
#pragma unroll
            for (int nf = 0; nf < 8; nf++) {
                int shn = nf * 8 + sh0;
                float s0 = sacc[mf][nf][0] * scl, s1 = sacc[mf][nf][1] * scl;
                float s2 = sacc[mf][nf][2] * scl, s3 = sacc[mf][nf][3] * scl;
                if ((mlo >> shn) & 1)       s0 = -3.402823466e38f;
                if ((mlo >> (shn + 1)) & 1) s1 = -3.402823466e38f;
                if ((mhi >> shn) & 1)       s2 = -3.402823466e38f;
                if ((mhi >> (shn + 1)) & 1) s3 = -3.402823466e38f;
                sacc[mf][nf][0] = s0; sacc[mf][nf][1] = s1;
                sacc[mf][nf][2] = s2; sacc[mf][nf][3] = s3;
                tm[2 * mf]     = fmaxf(tm[2 * mf], fmaxf(s0, s1));
                tm[2 * mf + 1] = fmaxf(tm[2 * mf + 1], fmaxf(s2, s3));
            }
        }
        float corr[4], mn[4];
#pragma unroll
        for (int i = 0; i < 4; i++) {
            tm[i] = fmaxf(tm[i], __shfl_xor_sync(0xffffffffu, tm[i], 1));
            tm[i] = fmaxf(tm[i], __shfl_xor_sync(0xffffffffu, tm[i], 2));
            mn[i] = fmaxf(mrun[i], tm[i]);
            corr[i] = __expf(mrun[i] - mn[i]);
            mrun[i] = mn[i];
        }
        uint32_t pfr[2][8][2];
        float ls[4] = {0.f, 0.f, 0.f, 0.f};
#pragma unroll
        for (int mf = 0; mf < 2; mf++) {
#pragma unroll
            for (int nf = 0; nf < 8; nf++) {
                float p0 = __expf(sacc[mf][nf][0] - mn[2 * mf]);
                float p1 = __expf(sacc[mf][nf][1] - mn[2 * mf]);
                float p2 = __expf(sacc[mf][nf][2] - mn[2 * mf + 1]);
                float p3 = __expf(sacc[mf][nf][3] - mn[2 * mf + 1]);
                ls[2 * mf]     += p0 + p1;
                ls[2 * mf + 1] += p2 + p3;
                pfr[mf][nf][0] = packh2(p0, p1);
                pfr[mf][nf][1] = packh2(p2, p3);
            }
        }
#pragma unroll
        for (int i = 0; i < 4; i++) {
            ls[i] += __shfl_xor_sync(0xffffffffu, ls[i], 1);
            ls[i] += __shfl_xor_sync(0xffffffffu, ls[i], 2);
            lrun[i] = lrun[i] * corr[i] + ls[i];
        }
#pragma unroll
        for (int mf = 0; mf < 2; mf++)
#pragma unroll
            for (int nf = 0; nf < 8; nf++) {
                oacc[mf][nf][0] *= corr[2 * mf];     oacc[mf][nf][1] *= corr[2 * mf];
                oacc[mf][nf][2] *= corr[2 * mf + 1]; oacc[mf][nf][3] *= corr[2 * mf + 1];
            }

        // ---- O += P V  (A fragments directly from pfr registers) ----
#pragma unroll
        for (int ks = 0; ks < 4; ks++) {
#pragma unroll
            for (int p = 0; p < 4; p++) {
                uint32_t bfr[4];
                LDSM_X4_T(bfr, vbase + ks * (16 * AROW) + p * 32);
#pragma unroll
                for (int sub = 0; sub < 2; sub++) {
                    int nf = 2 * p + sub;
                    uint32_t b0 = bfr[sub * 2], b1 = bfr[sub * 2 + 1];
#pragma unroll
                    for (int mf = 0; mf < 2; mf++)
                        MMA_F16(oacc[mf][nf],
                                pfr[mf][2 * ks][0], pfr[mf][2 * ks][1],
                                pfr[mf][2 * ks + 1][0], pfr[mf][2 * ks + 1][1],
                                b0, b1);
                }
            }
        }
    }
#undef A_ISSUE

    float inv[4];
#pragma unroll
    for (int i = 0; i < 4; i++) inv[i] = __fdividef(1.f, lrun[i]);
#pragma unroll
    for (int mf = 0; mf < 2; mf++) {
        size_t row = (size_t)b * NQ + qt * QTILE + wm + mf * 16 + g;
        __half* o1 = ctx + row * INNER + h * DH;
        __half* o2 = o1 + (size_t)8 * INNER;
#pragma unroll
        for (int nf = 0; nf < 8; nf++) {
            int c = nf * 8 + t4 * 2;
            *(__half2*)(o1 + c) = __floats2half2_rn(oacc[mf][nf][0] * inv[2 * mf],
                                                    oacc[mf][nf][1] * inv[2 * mf]);
            *(__half2*)(o2 + c) = __floats2half2_rn(oacc[mf][nf][2] * inv[2 * mf + 1],
                                                    oacc[mf][nf][3] * inv[2 * mf + 1]);
        }
    }
}

// ---------------- launcher ----------------
extern "C" void kernel_launch(void* const* d_in, const int* in_sizes, int n_in,
                              void* d_out, int out_size) {
    const float* x     = (const float*)d_in[0];
    const float* key_t = (const float*)d_in[1];
    const float* value = (const float*)d_in[2];
    const int*   mask  = (const int*)d_in[3];
    const float* Wq    = (const float*)d_in[4];
    const float* Wk    = (const float*)d_in[5];
    const float* Wv    = (const float*)d_in[6];
    const float* Wo    = (const float*)d_in[7];
    const float* gamma = (const float*)d_in[8];
    const float* beta  = (const float*)d_in[9];
    float* out = (float*)d_out;

    __half *xn, *q, *k, *v, *ctx, *wqt, *wkt, *wvt, *wot, *kin, *vin;
    unsigned long long* mb;
    cudaGetSymbolAddress((void**)&xn,  g_xn);
    cudaGetSymbolAddress((void**)&q,   g_q);
    cudaGetSymbolAddress((void**)&k,   g_k);
    cudaGetSymbolAddress((void**)&v,   g_v);
    cudaGetSymbolAddress((void**)&ctx, g_ctx);
    cudaGetSymbolAddress((void**)&wqt, g_wqt);
    cudaGetSymbolAddress((void**)&wkt, g_wkt);
    cudaGetSymbolAddress((void**)&wvt, g_wvt);
    cudaGetSymbolAddress((void**)&wot, g_wot);
    cudaGetSymbolAddress((void**)&kin, g_kin);
    cudaGetSymbolAddress((void**)&vin, g_vin);
    cudaGetSymbolAddress((void**)&mb,  g_mb);

    cudaFuncSetAttribute(attn_mma, cudaFuncAttributeMaxDynamicSharedMemorySize, ATTN_SMEM);
    cudaFuncSetAttribute(gemm_qkv, cudaFuncAttributeMaxDynamicSharedMemorySize, GT_SMEM);
    cudaFuncSetAttribute(gemm_out, cudaFuncAttributeMaxDynamicSharedMemorySize, GT_SMEM);

    prep_fused<<<25088, 256>>>(x, key_t, value, mask, Wq, Wk, Wv, Wo, gamma, beta,
                               xn, kin, vin, mb, wqt, wkt, wvt, wot);

    gemm_qkv<<<dim3(8, 160), 256, GT_SMEM>>>(xn, kin, vin, wqt, wkt, wvt, q, k, v);

    attn_mma<<<dim3(NQ / QTILE, HEADS, BATCH), 128, ATTN_SMEM>>>(q, k, v, mb, ctx);

    gemm_out<<<dim3(8, 32), 256, GT_SMEM>>>(ctx, wot, out);
}

// round 17
// speedup vs baseline: 1.1058x; 1.1058x over previous
#include <cuda_runtime.h>
#include <cuda_fp16.h>
#include <math.h>
#include <cstdint>

#define BATCH  4
#define NQ     1024
#define NKV    2048
#define DMODEL 1024
#define HEADS  16
#define DH     64
#define INNER  1024
#define KDIM   1024

// ---------------- scratch (no allocation allowed) ----------------
__device__ __half g_xn [BATCH * NQ  * DMODEL];
__device__ __half g_q  [BATCH * NQ  * INNER];
__device__ __half g_k  [BATCH * NKV * INNER];
__device__ __half g_v  [BATCH * NKV * INNER];
__device__ __half g_ctx[BATCH * NQ  * INNER];
__device__ __half g_wqt[KDIM * INNER];
__device__ __half g_wkt[KDIM * INNER];
__device__ __half g_wvt[KDIM * INNER];
__device__ __half g_wot[KDIM * INNER];
__device__ __half g_kin[BATCH * NKV * KDIM];
__device__ __half g_vin[BATCH * NKV * KDIM];
__device__ unsigned long long g_mb[BATCH * 32 * NQ];   // [b][kvblock][q] bitmask

__device__ __forceinline__ uint32_t smem_to_u32(const void* p) {
    uint32_t a;
    asm("{ .reg .u64 t; cvta.to.shared.u64 t, %1; cvt.u32.u64 %0, t; }" : "=r"(a) : "l"(p));
    return a;
}
__device__ __forceinline__ void cp_async16(uint32_t saddr, const void* g) {
    asm volatile("cp.async.cg.shared.global [%0], [%1], 16;" :: "r"(saddr), "l"(g));
}
#define CP_COMMIT() asm volatile("cp.async.commit_group;")
#define CP_WAIT(n)  asm volatile("cp.async.wait_group %0;" :: "n"(n) : "memory")

#define MMA_F16(acc, a0, a1, a2, a3, b0, b1) \
    asm volatile( \
        "mma.sync.aligned.m16n8k16.row.col.f32.f16.f16.f32 " \
        "{%0,%1,%2,%3}, {%4,%5,%6,%7}, {%8,%9}, {%0,%1,%2,%3};" \
        : "+f"((acc)[0]), "+f"((acc)[1]), "+f"((acc)[2]), "+f"((acc)[3]) \
        : "r"(a0), "r"(a1), "r"(a2), "r"(a3), "r"(b0), "r"(b1))

#define LDSM_X4(r, addr) \
    asm volatile("ldmatrix.sync.aligned.m8n8.x4.shared.b16 {%0,%1,%2,%3}, [%4];" \
        : "=r"((r)[0]), "=r"((r)[1]), "=r"((r)[2]), "=r"((r)[3]) : "r"(addr))

#define LDSM_X4_T(r, addr) \
    asm volatile("ldmatrix.sync.aligned.m8n8.x4.trans.shared.b16 {%0,%1,%2,%3}, [%4];" \
        : "=r"((r)[0]), "=r"((r)[1]), "=r"((r)[2]), "=r"((r)[3]) : "r"(addr))

__device__ __forceinline__ uint32_t packh2(float a, float b) {
    __half2 h = __floats2half2_rn(a, b);
    return *(uint32_t*)&h;
}

// ---------------- fused prep: transposes + rounds + maskbits + LN -------------
__global__ void prep_fused(const float* __restrict__ x,
                           const float* __restrict__ key_t, const float* __restrict__ value,
                           const int* __restrict__ mask,
                           const float* __restrict__ Wq, const float* __restrict__ Wk,
                           const float* __restrict__ Wv, const float* __restrict__ Wo,
                           const float* __restrict__ gamma, const float* __restrict__ beta,
                           __half* __restrict__ xn,
                           __half* __restrict__ kin, __half* __restrict__ vin,
                           unsigned long long* __restrict__ mb,
                           __half* __restrict__ wqt, __half* __restrict__ wkt,
                           __half* __restrict__ wvt, __half* __restrict__ wot) {
    __shared__ float smbuf[32][33];
    int bid = blockIdx.x, tid = threadIdx.x;

    if (bid < 4096) {                          // ---- weight transpose (to fp16)
        int w = bid >> 10, t = bid & 1023;
        const float* src = (w == 0) ? Wq : (w == 1) ? Wk : (w == 2) ? Wv : Wo;
        __half* dst      = (w == 0) ? wqt : (w == 1) ? wkt : (w == 2) ? wvt : wot;
        int bx = (t & 31) * 32, by = (t >> 5) * 32;
        int xI = tid & 31, yI = tid >> 5;      // 32 x 8
#pragma unroll
        for (int i = 0; i < 32; i += 8)
            smbuf[yI + i][xI] = src[(size_t)(by + yI + i) * KDIM + bx + xI];
        __syncthreads();
#pragma unroll
        for (int i = 0; i < 32; i += 8)
            dst[(size_t)(bx + yI + i) * KDIM + by + xI] = __float2half_rn(smbuf[xI][yI + i]);
    } else if (bid < 20480) {                  // ---- fp32 -> fp16 round
        int i0 = bid - 4096;
        const float* src = (i0 < 8192) ? key_t : value;
        __half* dst      = (i0 < 8192) ? kin : vin;
        int i = (i0 & 8191) * 256 + tid;
        float4 v = ((const float4*)src)[i];
        ((__half2*)dst)[2 * i]     = __floats2half2_rn(v.x, v.y);
        ((__half2*)dst)[2 * i + 1] = __floats2half2_rn(v.z, v.w);
    } else if (bid < 20992) {                  // ---- mask -> bitmask
        int idx = (bid - 20480) * 256 + tid;
        int b = idx >> 15, t = (idx >> 10) & 31, q = idx & 1023;
        const int4* p = (const int4*)(mask + (((size_t)b * NQ + q) * NKV + t * 64));
        unsigned long long bits = 0ull;
#pragma unroll
        for (int j = 0; j < 16; j++) {
            int4 v = p[j];
            bits |= (unsigned long long)(v.x != 0) << (4 * j);
            bits |= (unsigned long long)(v.y != 0) << (4 * j + 1);
            bits |= (unsigned long long)(v.z != 0) << (4 * j + 2);
            bits |= (unsigned long long)(v.w != 0) << (4 * j + 3);
        }
        mb[idx] = bits;
    } else {                                   // ---- LayerNorm (fp16 out)
        float* red = &smbuf[0][0];
        int row = bid - 20992;
        const float4* xr = (const float4*)(x + (size_t)row * DMODEL);
        float4 a = xr[tid];
        float s = a.x + a.y + a.z + a.w;
        float q = a.x * a.x + a.y * a.y + a.z * a.z + a.w * a.w;
#pragma unroll
        for (int off = 16; off; off >>= 1) {
            s += __shfl_xor_sync(0xffffffffu, s, off);
            q += __shfl_xor_sync(0xffffffffu, q, off);
        }
        if ((tid & 31) == 0) { red[tid >> 5] = s; red[8 + (tid >> 5)] = q; }
        __syncthreads();
        if (tid < 32) {
            float ss = (tid < 8) ? red[tid] : 0.f;
            float qq = (tid < 8) ? red[8 + tid] : 0.f;
#pragma unroll
            for (int off = 4; off; off >>= 1) {
                ss += __shfl_xor_sync(0xffffffffu, ss, off);
                qq += __shfl_xor_sync(0xffffffffu, qq, off);
            }
            if (tid == 0) { red[0] = ss; red[1] = qq; }
        }
        __syncthreads();
        float mu  = red[0] * (1.f / DMODEL);
        float var = red[1] * (1.f / DMODEL) - mu * mu;
        float inv = rsqrtf(var + 1e-5f);
        float4 g = ((const float4*)gamma)[tid];
        float4 b = ((const float4*)beta)[tid];
        __half2* yr = (__half2*)(xn + (size_t)row * DMODEL);
        yr[2 * tid]     = __floats2half2_rn((a.x - mu) * inv * g.x + b.x, (a.y - mu) * inv * g.y + b.y);
        yr[2 * tid + 1] = __floats2half2_rn((a.z - mu) * inv * g.z + b.z, (a.w - mu) * inv * g.w + b.w);
    }
}

// ---------------- fp16 mma GEMM core (cp.async, single-sync pipeline) ---------
#define GROW 144
#define GBUF_B (128 * GROW)
#define GT_SMEM (4 * GBUF_B)

__device__ __forceinline__ void gemm_core(const __half* __restrict__ Ab,
                                          const __half* __restrict__ Bb,
                                          void* __restrict__ Cout, size_t crowbase,
                                          int half_out, uint32_t sb, uint32_t* smw) {
    int tid = threadIdx.x, lane = tid & 31, wid = tid >> 5;
    int wm = (wid & 3) * 32, wn = (wid >> 2) * 64;
    int mrow = lane & 7, msel = lane >> 3;

    uint32_t aoffB = (uint32_t)((wm + (msel & 1) * 8 + mrow) * GROW + (msel >> 1) * 16);
    uint32_t boffB = (uint32_t)((wn + (msel >> 1) * 8 + mrow) * GROW + (msel & 1) * 16);

    float acc[2][8][4] = {};

#define G_ISSUE(it, bf) do { \
    uint32_t abase = sb + (bf) * GBUF_B; \
    uint32_t bbase = sb + (2 + (bf)) * GBUF_B; \
    _Pragma("unroll") \
    for (int i = 0; i < 4; i++) { \
        int idx = tid + i * 256; int rr = idx >> 3, qq = idx & 7; \
        cp_async16(abase + rr * GROW + qq * 16, Ab + (size_t)rr * KDIM + (it) * 64 + qq * 8); \
        cp_async16(bbase + rr * GROW + qq * 16, Bb + (size_t)rr * KDIM + (it) * 64 + qq * 8); \
    } \
    CP_COMMIT(); \
} while (0)

    G_ISSUE(0, 0);

    for (int it = 0; it < 16; it++) {
        int buf = it & 1;
        CP_WAIT(0);
        __syncthreads();
        if (it < 15) G_ISSUE(it + 1, buf ^ 1);

        uint32_t aaddr = sb + buf * GBUF_B + aoffB;
        uint32_t baddr = sb + (2 + buf) * GBUF_B + boffB;
#pragma unroll
        for (int ks = 0; ks < 4; ks++) {
            uint32_t afr[2][4];
            LDSM_X4(afr[0], aaddr + ks * 32);
            LDSM_X4(afr[1], aaddr + 16 * GROW + ks * 32);
#pragma unroll
            for (int p = 0; p < 4; p++) {
                uint32_t bfr[4];
                LDSM_X4(bfr, baddr + p * (16 * GROW) + ks * 32);
#pragma unroll
                for (int sub = 0; sub < 2; sub++) {
                    int nf = 2 * p + sub;
                    uint32_t b0 = bfr[sub * 2], b1 = bfr[sub * 2 + 1];
#pragma unroll
                    for (int mf = 0; mf < 2; mf++)
                        MMA_F16(acc[mf][nf], afr[mf][0], afr[mf][1], afr[mf][2], afr[mf][3], b0, b1);
                }
            }
        }
    }
#undef G_ISSUE

    if (half_out) {
        __half* Cb = (__half*)Cout + crowbase;
#pragma unroll
        for (int mf = 0; mf < 2; mf++) {
            int row = wm + mf * 16 + (lane >> 2);
#pragma unroll
            for (int nf = 0; nf < 8; nf++) {
                int col = wn + nf * 8 + (lane & 3) * 2;
                *(__half2*)(Cb + (size_t)row * 1024 + col) =
                    __floats2half2_rn(acc[mf][nf][0], acc[mf][nf][1]);
                *(__half2*)(Cb + (size_t)(row + 8) * 1024 + col) =
                    __floats2half2_rn(acc[mf][nf][2], acc[mf][nf][3]);
            }
        }
    } else {
        float* Cb = (float*)Cout + crowbase;
#pragma unroll
        for (int mf = 0; mf < 2; mf++) {
            int row = wm + mf * 16 + (lane >> 2);
#pragma unroll
            for (int nf = 0; nf < 8; nf++) {
                int col = wn + nf * 8 + (lane & 3) * 2;
                *(float2*)(Cb + (size_t)row * 1024 + col) = make_float2(acc[mf][nf][0], acc[mf][nf][1]);
                *(float2*)(Cb + (size_t)(row + 8) * 1024 + col) = make_float2(acc[mf][nf][2], acc[mf][nf][3]);
            }
        }
    }
}

// merged QKV GEMM: grid y 0..159
__global__ void __launch_bounds__(256, 2)
gemm_qkv(const __half* __restrict__ xn, const __half* __restrict__ kin, const __half* __restrict__ vin,
         const __half* __restrict__ wqt, const __half* __restrict__ wkt, const __half* __restrict__ wvt,
         __half* __restrict__ q, __half* __restrict__ k, __half* __restrict__ v) {
    extern __shared__ uint32_t smw[];
    uint32_t sb = smem_to_u32(smw);
    int y = blockIdx.y;
    const __half *A, *B;
    __half* C;
    int ytile;
    if (y < 32)      { A = xn;  B = wqt; C = q; ytile = y; }
    else if (y < 96) { A = kin; B = wkt; C = k; ytile = y - 32; }
    else             { A = vin; B = wvt; C = v; ytile = y - 96; }
    gemm_core(A + (size_t)(ytile * 128) * KDIM,
              B + (size_t)(blockIdx.x * 128) * KDIM,
              C, (size_t)(ytile * 128) * 1024 + blockIdx.x * 128, 1, sb, smw);
}

__global__ void __launch_bounds__(256, 2)
gemm_out(const __half* __restrict__ ctx, const __half* __restrict__ wot, float* __restrict__ out) {
    extern __shared__ uint32_t smw[];
    uint32_t sb = smem_to_u32(smw);
    gemm_core(ctx + (size_t)(blockIdx.y * 128) * KDIM,
              wot + (size_t)(blockIdx.x * 128) * KDIM,
              out, (size_t)(blockIdx.y * 128) * 1024 + blockIdx.x * 128, 0, sb, smw);
}

// ---------------- fp16 mma flash attention: 256 q x 64 kv, P in registers -----
#define QTILE 256
#define AROW 144
#define OFF_Q 0
#define SZ_Q  (QTILE * AROW)
#define OFF_K (SZ_Q)
#define SZ_KV (64 * AROW)
#define OFF_V (SZ_Q + 2 * SZ_KV)
#define OFF_M (SZ_Q + 4 * SZ_KV)             // 73728
#define ATTN_SMEM (OFF_M + 2 * 2048)         // 77824

__global__ void __launch_bounds__(256, 1)
attn_mma(const __half* __restrict__ Q,
         const __half* __restrict__ K,
         const __half* __restrict__ V,
         const unsigned long long* __restrict__ mbits,
         __half* __restrict__ ctx) {
    extern __shared__ uint32_t sw[];
    uint32_t sb = smem_to_u32(sw);

    int tid = threadIdx.x, lane = tid & 31, wid = tid >> 5;
    int b = blockIdx.z, h = blockIdx.y, qt = blockIdx.x;
    const int g = lane >> 2, t4 = lane & 3;
    const int wm = wid * 32;
    const int mrow = lane & 7, msel = lane >> 3;

    const uint32_t qa0 = sb + OFF_Q + (uint32_t)((wm + (msel & 1) * 8 + mrow) * AROW + (msel >> 1) * 16);
    const uint32_t qa1 = qa0 + 16 * AROW;
    const uint32_t kfragoff = (uint32_t)(((msel >> 1) * 8 + mrow) * AROW + (msel & 1) * 16);
    const uint32_t vfragoff = (uint32_t)(((msel & 1) * 8 + mrow) * AROW + (msel >> 1) * 16);

    const __half* Qb = Q + ((size_t)b * NQ + qt * QTILE) * INNER + h * DH;
    const __half* Kb = K + (size_t)b * NKV * INNER + h * DH;
    const __half* Vb = V + (size_t)b * NKV * INNER + h * DH;
    const char* Mb8 = (const char*)(mbits + (size_t)b * 32 * NQ) + (size_t)qt * QTILE * 8;

#pragma unroll
    for (int i = 0; i < 8; i++) {
        int idx = tid + i * 256;
        int r = idx >> 3, qq = idx & 7;
        cp_async16(sb + OFF_Q + r * AROW + qq * 16, Qb + (size_t)r * INNER + qq * 8);
    }
    CP_COMMIT();

#define A_ISSUE(t, bf) do { \
    uint32_t kb_ = sb + OFF_K + (bf) * SZ_KV; \
    uint32_t vb_ = sb + OFF_V + (bf) * SZ_KV; \
    uint32_t mb_ = sb + OFF_M + (bf) * 2048; \
    _Pragma("unroll") \
    for (int i = 0; i < 2; i++) { \
        int idx = tid + i * 256; int r = idx >> 3, qq = idx & 7; \
        cp_async16(kb_ + r * AROW + qq * 16, Kb + (size_t)((t) * 64 + r) * INNER + qq * 8); \
        cp_async16(vb_ + r * AROW + qq * 16, Vb + (size_t)((t) * 64 + r) * INNER + qq * 8); \
    } \
    if (tid < 128) cp_async16(mb_ + tid * 16, Mb8 + (size_t)(t) * NQ * 8 + tid * 16); \
    CP_COMMIT(); \
} while (0)

    A_ISSUE(0, 0);

    float oacc[2][8][4] = {};
    float mrun[4], lrun[4];
#pragma unroll
    for (int i = 0; i < 4; i++) { mrun[i] = -3.402823466e38f; lrun[i] = 0.f; }
    const float scl = 0.125f;

    for (int t = 0; t < NKV / 64; t++) {
        int buf = t & 1;
        CP_WAIT(0);
        __syncthreads();
        if (t < 31) A_ISSUE(t + 1, buf ^ 1);

        const uint32_t kbase = sb + OFF_K + buf * SZ_KV + kfragoff;
        const uint32_t vbase = sb + OFF_V + buf * SZ_KV + vfragoff;
        const unsigned long long* Msk =
            (const unsigned long long*)((const char*)sw + OFF_M + buf * 2048);

        // ---- S = Q K^T (warp: 32 x 64, 4 x k16) ----
        float sacc[2][8][4] = {};
#pragma unroll
        for (int ks = 0; ks < 4; ks++) {
            uint32_t afr[2][4];
            LDSM_X4(afr[0], qa0 + ks * 32);
            LDSM_X4(afr[1], qa1 + ks * 32);
#pragma unroll
            for (int p = 0; p < 4; p++) {
                uint32_t bfr[4];
                LDSM_X4(bfr, kbase + p * (16 * AROW) + ks * 32);
#pragma unroll
                for (int sub = 0; sub < 2; sub++) {
                    int nf = 2 * p + sub;
                    uint32_t b0 = bfr[sub * 2], b1 = bfr[sub * 2 + 1];
#pragma unroll
                    for (int mf = 0; mf < 2; mf++)
                        MMA_F16(sacc[mf][nf], afr[mf][0], afr[mf][1], afr[mf][2], afr[mf][3], b0, b1);
                }
            }
        }

        // ---- mask + scale + online softmax; P packed into registers ----
        unsigned long long mbm[4];
        mbm[0] = Msk[wm + g];
        mbm[1] = Msk[wm + g + 8];
        mbm[2] = Msk[wm + g + 16];
        mbm[3] = Msk[wm + g + 24];
        int sh0 = t4 * 2;

        float tm[4];
#pragma unroll
        for (int i = 0; i < 4; i++) tm[i] = -3.402823466e38f;
#pragma unroll
        for (int mf = 0; mf < 2; mf++) {
            unsigned long long mlo = mbm[2 * mf], mhi = mbm[2 * mf + 1];
#pragma unroll
            for (int nf = 0; nf < 8; nf++) {
                int shn = nf * 8 + sh0;
                float s0 = sacc[mf][nf][0] * scl, s1 = sacc[mf][nf][1] * scl;
                float s2 = sacc[mf][nf][2] * scl, s3 = sacc[mf][nf][3] * scl;
                if ((mlo >> shn) & 1)       s0 = -3.402823466e38f;
                if ((mlo >> (shn + 1)) & 1) s1 = -3.402823466e38f;
                if ((mhi >> shn) & 1)       s2 = -3.402823466e38f;
                if ((mhi >> (shn + 1)) & 1) s3 = -3.402823466e38f;
                sacc[mf][nf][0] = s0; sacc[mf][nf][1] = s1;
                sacc[mf][nf][2] = s2; sacc[mf][nf][3] = s3;
                tm[2 * mf]     = fmaxf(tm[2 * mf], fmaxf(s0, s1));
                tm[2 * mf + 1] = fmaxf(tm[2 * mf + 1], fmaxf(s2, s3));
            }
        }
        float corr[4], mn[4];
#pragma unroll
        for (int i = 0; i < 4; i++) {
            tm[i] = fmaxf(tm[i], __shfl_xor_sync(0xffffffffu, tm[i], 1));
            tm[i] = fmaxf(tm[i], __shfl_xor_sync(0xffffffffu, tm[i], 2));
            mn[i] = fmaxf(mrun[i], tm[i]);
            corr[i] = __expf(mrun[i] - mn[i]);
            mrun[i] = mn[i];
        }
        uint32_t pfr[2][8][2];
        float ls[4] = {0.f, 0.f, 0.f, 0.f};
#pragma unroll
        for (int mf = 0; mf < 2; mf++) {
#pragma unroll
            for (int nf = 0; nf < 8; nf++) {
                float p0 = __expf(sacc[mf][nf][0] - mn[2 * mf]);
                float p1 = __expf(sacc[mf][nf][1] - mn[2 * mf]);
                float p2 = __expf(sacc[mf][nf][2] - mn[2 * mf + 1]);
                float p3 = __expf(sacc[mf][nf][3] - mn[2 * mf + 1]);
                ls[2 * mf]     += p0 + p1;
                ls[2 * mf + 1] += p2 + p3;
                pfr[mf][nf][0] = packh2(p0, p1);
                pfr[mf][nf][1] = packh2(p2, p3);
            }
        }
#pragma unroll
        for (int i = 0; i < 4; i++) {
            ls[i] += __shfl_xor_sync(0xffffffffu, ls[i], 1);
            ls[i] += __shfl_xor_sync(0xffffffffu, ls[i], 2);
            lrun[i] = lrun[i] * corr[i] + ls[i];
        }
#pragma unroll
        for (int mf = 0; mf < 2; mf++)
#pragma unroll
            for (int nf = 0; nf < 8; nf++) {
                oacc[mf][nf][0] *= corr[2 * mf];     oacc[mf][nf][1] *= corr[2 * mf];
                oacc[mf][nf][2] *= corr[2 * mf + 1]; oacc[mf][nf][3] *= corr[2 * mf + 1];
            }

        // ---- O += P V  (A fragments directly from pfr registers) ----
#pragma unroll
        for (int ks = 0; ks < 4; ks++) {
#pragma unroll
            for (int p = 0; p < 4; p++) {
                uint32_t bfr[4];
                LDSM_X4_T(bfr, vbase + ks * (16 * AROW) + p * 32);
#pragma unroll
                for (int sub = 0; sub < 2; sub++) {
                    int nf = 2 * p + sub;
                    uint32_t b0 = bfr[sub * 2], b1 = bfr[sub * 2 + 1];
#pragma unroll
                    for (int mf = 0; mf < 2; mf++)
                        MMA_F16(oacc[mf][nf],
                                pfr[mf][2 * ks][0], pfr[mf][2 * ks][1],
                                pfr[mf][2 * ks + 1][0], pfr[mf][2 * ks + 1][1],
                                b0, b1);
                }
            }
        }
    }
#undef A_ISSUE

    float inv[4];
#pragma unroll
    for (int i = 0; i < 4; i++) inv[i] = __fdividef(1.f, lrun[i]);
#pragma unroll
    for (int mf = 0; mf < 2; mf++) {
        size_t row = (size_t)b * NQ + qt * QTILE + wm + mf * 16 + g;
        __half* o1 = ctx + row * INNER + h * DH;
        __half* o2 = o1 + (size_t)8 * INNER;
#pragma unroll
        for (int nf = 0; nf < 8; nf++) {
            int c = nf * 8 + t4 * 2;
            *(__half2*)(o1 + c) = __floats2half2_rn(oacc[mf][nf][0] * inv[2 * mf],
                                                    oacc[mf][nf][1] * inv[2 * mf]);
            *(__half2*)(o2 + c) = __floats2half2_rn(oacc[mf][nf][2] * inv[2 * mf + 1],
                                                    oacc[mf][nf][3] * inv[2 * mf + 1]);
        }
    }
}

// ---------------- launcher ----------------
extern "C" void kernel_launch(void* const* d_in, const int* in_sizes, int n_in,
                              void* d_out, int out_size) {
    const float* x     = (const float*)d_in[0];
    const float* key_t = (const float*)d_in[1];
    const float* value = (const float*)d_in[2];
    const int*   mask  = (const int*)d_in[3];
    const float* Wq    = (const float*)d_in[4];
    const float* Wk    = (const float*)d_in[5];
    const float* Wv    = (const float*)d_in[6];
    const float* Wo    = (const float*)d_in[7];
    const float* gamma = (const float*)d_in[8];
    const float* beta  = (const float*)d_in[9];
    float* out = (float*)d_out;

    __half *xn, *q, *k, *v, *ctx, *wqt, *wkt, *wvt, *wot, *kin, *vin;
    unsigned long long* mb;
    cudaGetSymbolAddress((void**)&xn,  g_xn);
    cudaGetSymbolAddress((void**)&q,   g_q);
    cudaGetSymbolAddress((void**)&k,   g_k);
    cudaGetSymbolAddress((void**)&v,   g_v);
    cudaGetSymbolAddress((void**)&ctx, g_ctx);
    cudaGetSymbolAddress((void**)&wqt, g_wqt);
    cudaGetSymbolAddress((void**)&wkt, g_wkt);
    cudaGetSymbolAddress((void**)&wvt, g_wvt);
    cudaGetSymbolAddress((void**)&wot, g_wot);
    cudaGetSymbolAddress((void**)&kin, g_kin);
    cudaGetSymbolAddress((void**)&vin, g_vin);
    cudaGetSymbolAddress((void**)&mb,  g_mb);

    cudaFuncSetAttribute(attn_mma, cudaFuncAttributeMaxDynamicSharedMemorySize, ATTN_SMEM);
    cudaFuncSetAttribute(gemm_qkv, cudaFuncAttributeMaxDynamicSharedMemorySize, GT_SMEM);
    cudaFuncSetAttribute(gemm_out, cudaFuncAttributeMaxDynamicSharedMemorySize, GT_SMEM);

    prep_fused<<<25088, 256>>>(x, key_t, value, mask, Wq, Wk, Wv, Wo, gamma, beta,
                               xn, kin, vin, mb, wqt, wkt, wvt, wot);

    gemm_qkv<<<dim3(8, 160), 256, GT_SMEM>>>(xn, kin, vin, wqt, wkt, wvt, q, k, v);

    attn_mma<<<dim3(NQ / QTILE, HEADS, BATCH), 256, ATTN_SMEM>>>(q, k, v, mb, ctx);

    gemm_out<<<dim3(8, 32), 256, GT_SMEM>>>(ctx, wot, out);
}